// round 1
// baseline (speedup 1.0000x reference)
#include <cuda_runtime.h>
#include <cuda_bf16.h>

#define BATCH   4096
#define DIM     256
#define NROWS   8192            // 2*BATCH
#define TM      64              // tile rows/cols
#define NTILES  (NROWS / TM)    // 128
#define STRIDE  257             // pad-1 row stride in shared (conflict-free)

// Scratch (no allocations allowed): normalized Z and per-CTA loss partials.
__device__ float g_Z[NROWS * DIM];
__device__ float g_partial[NTILES];

// ---------------------------------------------------------------------------
// Kernel 1: L2-normalize rows of [z_i; z_j] -> g_Z.  One block (64 thr) / row.
// ---------------------------------------------------------------------------
__global__ void ntx_norm_kernel(const float* __restrict__ zi,
                                const float* __restrict__ zj) {
    int row = blockIdx.x;
    const float* src = (row < BATCH) ? (zi + (size_t)row * DIM)
                                     : (zj + (size_t)(row - BATCH) * DIM);
    int t = threadIdx.x;  // 0..63, each handles one float4 (DIM/4 = 64)
    float4 v = reinterpret_cast<const float4*>(src)[t];
    float ss = v.x * v.x + v.y * v.y + v.z * v.z + v.w * v.w;
    #pragma unroll
    for (int m = 16; m >= 1; m >>= 1)
        ss += __shfl_xor_sync(0xffffffffu, ss, m);
    __shared__ float warpsum[2];
    if ((t & 31) == 0) warpsum[t >> 5] = ss;
    __syncthreads();
    float inv = 1.0f / sqrtf(warpsum[0] + warpsum[1]);
    float4 o;
    o.x = v.x * inv; o.y = v.y * inv; o.z = v.z * inv; o.w = v.w * inv;
    reinterpret_cast<float4*>(g_Z + (size_t)row * DIM)[t] = o;
}

// ---------------------------------------------------------------------------
// Kernel 2: fused sim-GEMM + logsumexp.
// 128 CTAs x 256 threads. CTA owns 64 rows (A tile resident in SMEM, full K),
// streams 128 column tiles of 64. 16x16 thread grid, 4x4 micro-tile with
// STRIDED row/col mapping (ty+16i, tx+16j) -> unit-stride lane addressing in
// SMEM (pad-1) -> conflict-free scalar LDS.
// sim in [-2,2] => no max shift needed. Diagonal included in the sum and
// subtracted as exp(s_ii) at the end; positive sim[i, i +/- BATCH] captured.
// ---------------------------------------------------------------------------
__global__ void __launch_bounds__(256, 1) ntx_main_kernel() {
    extern __shared__ float sm[];
    float* As     = sm;                      // [64][257]
    float* Bs     = As + TM * STRIDE;        // [64][257]
    float* diagv  = Bs + TM * STRIDE;        // [64]
    float* posv   = diagv + TM;              // [64]
    float* rowsum = posv + TM;               // [64]
    float* lossv  = rowsum + TM;             // [64]

    const int tid = threadIdx.x;
    const int tx  = tid & 15;
    const int ty  = tid >> 4;
    const int rowBase = blockIdx.x * TM;

    // Load A tile (64 rows x 256 K). Consecutive tid -> consecutive k:
    // coalesced global reads, conflict-free smem writes.
    for (int idx = tid; idx < TM * DIM; idx += 256) {
        int r = idx >> 8, k = idx & 255;
        As[r * STRIDE + k] = g_Z[(size_t)(rowBase + r) * DIM + k];
    }

    float sumexp[4] = {0.f, 0.f, 0.f, 0.f};

    for (int cb = 0; cb < NTILES; cb++) {
        const int colBase = cb * TM;
        __syncthreads();  // guards As (first iter) / Bs reuse (later iters)
        for (int idx = tid; idx < TM * DIM; idx += 256) {
            int c = idx >> 8, k = idx & 255;
            Bs[c * STRIDE + k] = g_Z[(size_t)(colBase + c) * DIM + k];
        }
        __syncthreads();

        float acc[4][4];
        #pragma unroll
        for (int i = 0; i < 4; i++)
            #pragma unroll
            for (int j = 0; j < 4; j++) acc[i][j] = 0.f;

        #pragma unroll 8
        for (int k = 0; k < DIM; k++) {
            float a[4], b[4];
            #pragma unroll
            for (int i = 0; i < 4; i++) a[i] = As[(ty + 16 * i) * STRIDE + k];
            #pragma unroll
            for (int j = 0; j < 4; j++) b[j] = Bs[(tx + 16 * j) * STRIDE + k];
            #pragma unroll
            for (int i = 0; i < 4; i++)
                #pragma unroll
                for (int j = 0; j < 4; j++) acc[i][j] += a[i] * b[j];
        }

        // Epilogue: logits = dot / T = dot * 2; accumulate exp, grab diag+pos.
        #pragma unroll
        for (int i = 0; i < 4; i++) {
            const int gr  = rowBase + ty + 16 * i;
            const int pos = (gr < BATCH) ? gr + BATCH : gr - BATCH;
            float se = 0.f;
            #pragma unroll
            for (int j = 0; j < 4; j++) {
                const int gc = colBase + tx + 16 * j;
                const float s = acc[i][j] * 2.0f;
                se += __expf(s);
                if (gc == gr)  diagv[ty + 16 * i] = s;
                if (gc == pos) posv[ty + 16 * i]  = s;
            }
            sumexp[i] += se;
        }
    }

    // Reduce sumexp across the 16 tx lanes of each row (xor<=8 stays in-group).
    #pragma unroll
    for (int i = 0; i < 4; i++) {
        float v = sumexp[i];
        #pragma unroll
        for (int m = 8; m >= 1; m >>= 1)
            v += __shfl_xor_sync(0xffffffffu, v, m);
        if (tx == 0) rowsum[ty + 16 * i] = v;
    }
    __syncthreads();

    if (tid < TM) {
        float tot = rowsum[tid] - __expf(diagv[tid]);  // mask self-similarity
        lossv[tid] = logf(tot) - posv[tid];            // lse - positive
    }
    __syncthreads();

    if (tid == 0) {  // deterministic per-CTA sum
        float s = 0.f;
        for (int r = 0; r < TM; r++) s += lossv[r];
        g_partial[blockIdx.x] = s;
    }
}

// ---------------------------------------------------------------------------
// Kernel 3: deterministic final reduction -> mean loss.
// ---------------------------------------------------------------------------
__global__ void ntx_final_kernel(float* __restrict__ out) {
    if (threadIdx.x == 0) {
        float s = 0.f;
        for (int i = 0; i < NTILES; i++) s += g_partial[i];
        out[0] = s / (float)NROWS;
    }
}

// ---------------------------------------------------------------------------
extern "C" void kernel_launch(void* const* d_in, const int* in_sizes, int n_in,
                              void* d_out, int out_size) {
    const float* zi = (const float*)d_in[0];
    const float* zj = (const float*)d_in[1];
    float* out = (float*)d_out;

    const int smem_bytes = (2 * TM * STRIDE + 4 * TM) * sizeof(float); // 132608
    cudaFuncSetAttribute(ntx_main_kernel,
                         cudaFuncAttributeMaxDynamicSharedMemorySize, smem_bytes);

    ntx_norm_kernel<<<NROWS, 64>>>(zi, zj);
    ntx_main_kernel<<<NTILES, 256, smem_bytes>>>();
    ntx_final_kernel<<<1, 32>>>(out);
}

// round 3
// speedup vs baseline: 8.4183x; 8.4183x over previous
#include <cuda_runtime.h>
#include <cuda_bf16.h>
#include <cstdint>

#define BATCH   4096
#define DIM     256
#define NROWS   8192
#define TM      128
#define TN      128
#define TILES   32            // column tiles per CTA (half of 8192 / 128)
#define KSTEPS  16            // K=256 / k16
#define RSTRIDE 528           // smem row stride bytes (512 + 16 pad)
#define ATILE   (128 * RSTRIDE)

// Scratch (no allocations allowed)
__device__ __nv_bfloat16 g_Zb[NROWS * DIM];   // normalized rows, bf16
__device__ float g_rowsum[2][NROWS];          // per-half sum of exp
__device__ float g_blocksum[1024];

__device__ __forceinline__ uint32_t smem_u32(const void* p) {
    uint32_t a;
    asm("{ .reg .u64 t; cvta.to.shared.u64 t, %1; cvt.u32.u64 %0, t; }"
        : "=r"(a) : "l"(p));
    return a;
}
#define CP16(dst, src) \
    asm volatile("cp.async.cg.shared.global [%0], [%1], 16;" \
                 :: "r"(dst), "l"(src) : "memory")
#define CP_COMMIT() asm volatile("cp.async.commit_group;" ::: "memory")
#define CP_WAIT(n)  asm volatile("cp.async.wait_group %0;" :: "n"(n) : "memory")

#define LDSM_X4(r0, r1, r2, r3, a)                                         \
    asm volatile("ldmatrix.sync.aligned.m8n8.x4.shared.b16 "               \
                 "{%0,%1,%2,%3}, [%4];"                                    \
                 : "=r"(r0), "=r"(r1), "=r"(r2), "=r"(r3) : "r"(a))

#define MMA16816(c, a, b)                                                  \
    asm volatile("mma.sync.aligned.m16n8k16.row.col.f32.bf16.bf16.f32 "    \
                 "{%0,%1,%2,%3}, {%4,%5,%6,%7}, {%8,%9}, {%0,%1,%2,%3};"   \
                 : "+f"((c)[0]), "+f"((c)[1]), "+f"((c)[2]), "+f"((c)[3])  \
                 : "r"((a)[0]), "r"((a)[1]), "r"((a)[2]), "r"((a)[3]),     \
                   "r"((b)[0]), "r"((b)[1]))

// ---------------------------------------------------------------------------
// Kernel 1: L2-normalize rows of [z_i; z_j] -> bf16 g_Zb. Warp per row.
// ---------------------------------------------------------------------------
__global__ void ntx_norm_kernel(const float* __restrict__ zi,
                                const float* __restrict__ zj) {
    int wid = threadIdx.x >> 5, lid = threadIdx.x & 31;
    int row = blockIdx.x * 8 + wid;
    const float* src = (row < BATCH) ? (zi + (size_t)row * DIM)
                                     : (zj + (size_t)(row - BATCH) * DIM);
    float4 a = reinterpret_cast<const float4*>(src)[lid * 2];
    float4 b = reinterpret_cast<const float4*>(src)[lid * 2 + 1];
    float ss = a.x*a.x + a.y*a.y + a.z*a.z + a.w*a.w
             + b.x*b.x + b.y*b.y + b.z*b.z + b.w*b.w;
    #pragma unroll
    for (int m = 16; m >= 1; m >>= 1) ss += __shfl_xor_sync(0xffffffffu, ss, m);
    float inv = rsqrtf(ss);
    __nv_bfloat162 p0 = __floats2bfloat162_rn(a.x*inv, a.y*inv);
    __nv_bfloat162 p1 = __floats2bfloat162_rn(a.z*inv, a.w*inv);
    __nv_bfloat162 p2 = __floats2bfloat162_rn(b.x*inv, b.y*inv);
    __nv_bfloat162 p3 = __floats2bfloat162_rn(b.z*inv, b.w*inv);
    uint4 o;
    o.x = *(uint32_t*)&p0; o.y = *(uint32_t*)&p1;
    o.z = *(uint32_t*)&p2; o.w = *(uint32_t*)&p3;
    reinterpret_cast<uint4*>(g_Zb + (size_t)row * DIM)[lid] = o;
}

// ---------------------------------------------------------------------------
// Kernel 2: bf16 mma.sync GEMM + fused exp row-sums.
// grid 128: CTA -> (M-tile = bid>>1 of 128 rows) x (column half = bid&1).
// A resident in SMEM, B double-buffered (cp.async). Warp grid 4(M) x 2(N),
// warp tile 32x64 -> 2 m16-tiles x 8 n8-tiles. Row stride 528B: ldmatrix
// conflict-free (8 consecutive rows start on banks 0,4,...,28).
// ---------------------------------------------------------------------------
__global__ void __launch_bounds__(256, 1) ntx_gemm_kernel() {
    extern __shared__ char smem[];
    uint32_t sb = smem_u32(smem);
    float* part = reinterpret_cast<float*>(smem);     // [2][128] partial rowsums
    const uint32_t Aoff = sb + 1024;
    const uint32_t Boff[2] = { Aoff + ATILE, Aoff + 2 * ATILE };

    const int tid = threadIdx.x, wid = tid >> 5, lane = tid & 31;
    const int wm = wid >> 1, wn = wid & 1;            // 4 x 2 warp grid
    const int mtile = blockIdx.x >> 1, half = blockIdx.x & 1;
    const int rowBase = mtile * TM, colBase = half * 4096;

    // ---- async A load (own group) ----
    {
        const char* gsrc = reinterpret_cast<const char*>(g_Zb)
                         + (size_t)rowBase * 512;
        #pragma unroll
        for (int i = 0; i < 16; i++) {
            int idx = tid + i * 256, r = idx >> 5, c = idx & 31;
            CP16(Aoff + r * RSTRIDE + c * 16, gsrc + r * 512 + c * 16);
        }
        CP_COMMIT();
    }
    // ---- B tile 0 ----
    {
        const char* gsrc = reinterpret_cast<const char*>(g_Zb)
                         + (size_t)colBase * 512;
        #pragma unroll
        for (int i = 0; i < 16; i++) {
            int idx = tid + i * 256, r = idx >> 5, c = idx & 31;
            CP16(Boff[0] + r * RSTRIDE + c * 16, gsrc + r * 512 + c * 16);
        }
        CP_COMMIT();
    }

    // ldmatrix per-thread base addresses
    // A: row = wm*32 + mt*16 + (lane&15), k-elems = ks*16 + (lane>>4)*8
    const uint32_t Arow = Aoff + (wm * 32 + (lane & 15)) * RSTRIDE
                        + ((lane >> 4) << 4);
    // B(x4 pair p covers n-tiles 2p,2p+1):
    // row = wn*64 + (2p + (lane>>4))*8 + (lane&7), k-elems = ks*16 + ((lane>>3)&1)*8
    const uint32_t BrowRel = (wn * 64 + ((lane >> 4) << 3) + (lane & 7)) * RSTRIDE
                           + (((lane >> 3) & 1) << 4);

    float rsum[2][2] = {{0.f, 0.f}, {0.f, 0.f}};      // [mt][row g / g+8]

    for (int t = 0; t < TILES; t++) {
        const int buf = t & 1, nb = buf ^ 1;
        if (t + 1 < TILES) {
            const char* gsrc = reinterpret_cast<const char*>(g_Zb)
                             + (size_t)(colBase + (t + 1) * TN) * 512;
            #pragma unroll
            for (int i = 0; i < 16; i++) {
                int idx = tid + i * 256, r = idx >> 5, c = idx & 31;
                CP16(Boff[nb] + r * RSTRIDE + c * 16, gsrc + r * 512 + c * 16);
            }
            CP_COMMIT();
            CP_WAIT(1);             // A + B[buf] complete, prefetch in flight
        } else {
            CP_WAIT(0);
        }
        __syncthreads();

        float acc[2][8][4];
        #pragma unroll
        for (int mt = 0; mt < 2; mt++)
            #pragma unroll
            for (int nt = 0; nt < 8; nt++)
                #pragma unroll
                for (int c = 0; c < 4; c++) acc[mt][nt][c] = 0.f;

        const uint32_t Brow = Boff[buf] + BrowRel;
        #pragma unroll
        for (int ks = 0; ks < KSTEPS; ks++) {
            uint32_t a[2][4], b[4][4];
            #pragma unroll
            for (int mt = 0; mt < 2; mt++)
                LDSM_X4(a[mt][0], a[mt][1], a[mt][2], a[mt][3],
                        Arow + mt * 16 * RSTRIDE + ks * 32);
            #pragma unroll
            for (int p = 0; p < 4; p++)
                LDSM_X4(b[p][0], b[p][1], b[p][2], b[p][3],
                        Brow + p * 16 * RSTRIDE + ks * 32);
            #pragma unroll
            for (int mt = 0; mt < 2; mt++)
                #pragma unroll
                for (int p = 0; p < 4; p++) {
                    MMA16816(acc[mt][2 * p],     a[mt], (&b[p][0]));
                    MMA16816(acc[mt][2 * p + 1], a[mt], (&b[p][2]));
                }
        }
        __syncthreads();            // B[buf] fully consumed before next fill

        // Fused epilogue: exp(2*dot) = 2^(dot * 2*log2(e)); accumulate row sums.
        #pragma unroll
        for (int mt = 0; mt < 2; mt++) {
            float s0 = 0.f, s1 = 0.f;
            #pragma unroll
            for (int nt = 0; nt < 8; nt++) {
                float e;
                asm("ex2.approx.f32 %0, %1;" : "=f"(e)
                    : "f"(acc[mt][nt][0] * 2.8853900817779268f)); s0 += e;
                asm("ex2.approx.f32 %0, %1;" : "=f"(e)
                    : "f"(acc[mt][nt][1] * 2.8853900817779268f)); s0 += e;
                asm("ex2.approx.f32 %0, %1;" : "=f"(e)
                    : "f"(acc[mt][nt][2] * 2.8853900817779268f)); s1 += e;
                asm("ex2.approx.f32 %0, %1;" : "=f"(e)
                    : "f"(acc[mt][nt][3] * 2.8853900817779268f)); s1 += e;
            }
            rsum[mt][0] += s0;
            rsum[mt][1] += s1;
        }
    }

    // Reduce across the 4 lanes of each quad (they share rows).
    #pragma unroll
    for (int mt = 0; mt < 2; mt++)
        #pragma unroll
        for (int h = 0; h < 2; h++) {
            float v = rsum[mt][h];
            v += __shfl_xor_sync(0xffffffffu, v, 1);
            v += __shfl_xor_sync(0xffffffffu, v, 2);
            rsum[mt][h] = v;
        }
    __syncthreads();                // part[] aliases smem start (no tile use now)
    if ((lane & 3) == 0) {
        int g = lane >> 2;
        #pragma unroll
        for (int mt = 0; mt < 2; mt++)
            #pragma unroll
            for (int h = 0; h < 2; h++)
                part[wn * 128 + wm * 32 + mt * 16 + h * 8 + g] = rsum[mt][h];
    }
    __syncthreads();
    if (tid < 128)
        g_rowsum[half][rowBase + tid] = part[tid] + part[128 + tid];
}

// ---------------------------------------------------------------------------
// Kernel 3: per-row loss. Recompute self-dot & positive exactly from bf16 Z
// (fp32 products of the same bf16 values the MMA consumed).
// ---------------------------------------------------------------------------
__global__ void ntx_loss_kernel() {
    int wid = threadIdx.x >> 5, lid = threadIdx.x & 31;
    int row = blockIdx.x * 8 + wid;
    int pos = (row < BATCH) ? row + BATCH : row - BATCH;
    uint4 r4 = reinterpret_cast<const uint4*>(g_Zb + (size_t)row * DIM)[lid];
    uint4 p4 = reinterpret_cast<const uint4*>(g_Zb + (size_t)pos * DIM)[lid];
    const __nv_bfloat162* rp = reinterpret_cast<const __nv_bfloat162*>(&r4);
    const __nv_bfloat162* pp = reinterpret_cast<const __nv_bfloat162*>(&p4);
    float dself = 0.f, dpos = 0.f;
    #pragma unroll
    for (int j = 0; j < 4; j++) {
        float2 fr = __bfloat1622float2(rp[j]);
        float2 fp = __bfloat1622float2(pp[j]);
        dself += fr.x * fr.x + fr.y * fr.y;
        dpos  += fr.x * fp.x + fr.y * fp.y;
    }
    #pragma unroll
    for (int m = 16; m >= 1; m >>= 1) {
        dself += __shfl_xor_sync(0xffffffffu, dself, m);
        dpos  += __shfl_xor_sync(0xffffffffu, dpos,  m);
    }
    __shared__ float ls[8];
    if (lid == 0) {
        float rsum = g_rowsum[0][row] + g_rowsum[1][row];
        ls[wid] = logf(rsum - expf(2.f * dself)) - 2.f * dpos;
    }
    __syncthreads();
    if (threadIdx.x == 0) {
        float s = 0.f;
        #pragma unroll
        for (int i = 0; i < 8; i++) s += ls[i];
        g_blocksum[blockIdx.x] = s;
    }
}

__global__ void ntx_final_kernel(float* __restrict__ out) {
    __shared__ float sm[256];
    int t = threadIdx.x;
    sm[t] = g_blocksum[t] + g_blocksum[t + 256]
          + g_blocksum[t + 512] + g_blocksum[t + 768];
    __syncthreads();
    for (int w = 128; w >= 1; w >>= 1) {
        if (t < w) sm[t] += sm[t + w];
        __syncthreads();
    }
    if (t == 0) out[0] = sm[0] / (float)NROWS;
}

// ---------------------------------------------------------------------------
extern "C" void kernel_launch(void* const* d_in, const int* in_sizes, int n_in,
                              void* d_out, int out_size) {
    const float* zi = (const float*)d_in[0];
    const float* zj = (const float*)d_in[1];
    float* out = (float*)d_out;

    const int smem_bytes = 1024 + 3 * ATILE;   // 1024 + 202752 = 203776
    cudaFuncSetAttribute(ntx_gemm_kernel,
                         cudaFuncAttributeMaxDynamicSharedMemorySize, smem_bytes);

    ntx_norm_kernel<<<1024, 256>>>(zi, zj);
    ntx_gemm_kernel<<<128, 256, smem_bytes>>>();
    ntx_loss_kernel<<<1024, 256>>>();
    ntx_final_kernel<<<1, 256>>>(out);
}

// round 5
// speedup vs baseline: 11.5195x; 1.3684x over previous
#include <cuda_runtime.h>
#include <cuda_bf16.h>
#include <cuda_fp16.h>
#include <cstdint>

#define BATCH   4096
#define DIM     256
#define NROWS   8192
#define TM      128
#define TN      128
#define TILES   32            // column tiles per CTA (half of 8192 / 128)
#define KSTEPS  8             // K=256 / k32
#define RS8     272           // smem row stride bytes (256 + 16 pad)
#define TILE8   (128 * RS8)   // 34816 B per tile
// logits = dot(z,z')/T = acc/(16*16) * 2 ; ex2 arg = acc * 2*log2(e)/256
#define EXC     0.011271055006945026f

// Scratch (no allocations allowed)
__device__ __nv_bfloat16 g_Zb[NROWS * DIM];   // normalized rows, bf16 (loss krnl)
__device__ uint8_t g_Z8[NROWS * DIM];         // normalized rows * 16, e4m3 (GEMM)
__device__ float g_rowsum[2][NROWS];
__device__ float g_blocksum[1024];

__device__ __forceinline__ uint32_t smem_u32(const void* p) {
    uint32_t a;
    asm("{ .reg .u64 t; cvta.to.shared.u64 t, %1; cvt.u32.u64 %0, t; }"
        : "=r"(a) : "l"(p));
    return a;
}
#define CP16(dst, src) \
    asm volatile("cp.async.cg.shared.global [%0], [%1], 16;" \
                 :: "r"(dst), "l"(src) : "memory")
#define CP_COMMIT() asm volatile("cp.async.commit_group;" ::: "memory")
#define CP_WAIT(n)  asm volatile("cp.async.wait_group %0;" :: "n"(n) : "memory")

#define LDSM_X4(r0, r1, r2, r3, a)                                         \
    asm volatile("ldmatrix.sync.aligned.m8n8.x4.shared.b16 "               \
                 "{%0,%1,%2,%3}, [%4];"                                    \
                 : "=r"(r0), "=r"(r1), "=r"(r2), "=r"(r3) : "r"(a))

#define MMA_FP8(c, a, b0, b1)                                              \
    asm volatile("mma.sync.aligned.m16n8k32.row.col.f32.e4m3.e4m3.f32 "    \
                 "{%0,%1,%2,%3}, {%4,%5,%6,%7}, {%8,%9}, {%0,%1,%2,%3};"   \
                 : "+f"((c)[0]), "+f"((c)[1]), "+f"((c)[2]), "+f"((c)[3])  \
                 : "r"((a)[0]), "r"((a)[1]), "r"((a)[2]), "r"((a)[3]),     \
                   "r"(b0), "r"(b1))

// pack 4 floats -> 4 e4m3 bytes (satfinite), byte0 = x0
__device__ __forceinline__ uint32_t pack_e4m3x4(float x0, float x1,
                                                float x2, float x3) {
    uint32_t w;
    asm("{ .reg .b16 s0, s1;\n\t"
        "cvt.rn.satfinite.e4m3x2.f32 s0, %2, %1;\n\t"   // a->hi, b->lo
        "cvt.rn.satfinite.e4m3x2.f32 s1, %4, %3;\n\t"
        "mov.b32 %0, {s0, s1}; }"
        : "=r"(w) : "f"(x0), "f"(x1), "f"(x2), "f"(x3));
    return w;
}
// unpack 4 e4m3 bytes -> float4 (via f16x2)
__device__ __forceinline__ float4 unpack_e4m3x4(uint32_t w) {
    uint32_t h0, h1;
    asm("{ .reg .b16 a, b;\n\t"
        "mov.b32 {a, b}, %2;\n\t"
        "cvt.rn.f16x2.e4m3x2 %0, a;\n\t"
        "cvt.rn.f16x2.e4m3x2 %1, b; }"
        : "=r"(h0), "=r"(h1) : "r"(w));
    __half2 v0 = *reinterpret_cast<__half2*>(&h0);
    __half2 v1 = *reinterpret_cast<__half2*>(&h1);
    float2 f0 = __half22float2(v0), f1 = __half22float2(v1);
    return make_float4(f0.x, f0.y, f1.x, f1.y);
}

// ---------------------------------------------------------------------------
// Kernel 1: L2-normalize rows -> bf16 (exact path) + e4m3*16 (GEMM path).
// ---------------------------------------------------------------------------
__global__ void ntx_norm_kernel(const float* __restrict__ zi,
                                const float* __restrict__ zj) {
    int wid = threadIdx.x >> 5, lid = threadIdx.x & 31;
    int row = blockIdx.x * 8 + wid;
    const float* src = (row < BATCH) ? (zi + (size_t)row * DIM)
                                     : (zj + (size_t)(row - BATCH) * DIM);
    float4 a = reinterpret_cast<const float4*>(src)[lid * 2];
    float4 b = reinterpret_cast<const float4*>(src)[lid * 2 + 1];
    float ss = a.x*a.x + a.y*a.y + a.z*a.z + a.w*a.w
             + b.x*b.x + b.y*b.y + b.z*b.z + b.w*b.w;
    #pragma unroll
    for (int m = 16; m >= 1; m >>= 1) ss += __shfl_xor_sync(0xffffffffu, ss, m);
    float inv = rsqrtf(ss);
    float s16 = inv * 16.0f;

    __nv_bfloat162 p0 = __floats2bfloat162_rn(a.x*inv, a.y*inv);
    __nv_bfloat162 p1 = __floats2bfloat162_rn(a.z*inv, a.w*inv);
    __nv_bfloat162 p2 = __floats2bfloat162_rn(b.x*inv, b.y*inv);
    __nv_bfloat162 p3 = __floats2bfloat162_rn(b.z*inv, b.w*inv);
    uint4 o;
    o.x = *(uint32_t*)&p0; o.y = *(uint32_t*)&p1;
    o.z = *(uint32_t*)&p2; o.w = *(uint32_t*)&p3;
    reinterpret_cast<uint4*>(g_Zb + (size_t)row * DIM)[lid] = o;

    uint2 q;
    q.x = pack_e4m3x4(a.x*s16, a.y*s16, a.z*s16, a.w*s16);
    q.y = pack_e4m3x4(b.x*s16, b.y*s16, b.z*s16, b.w*s16);
    reinterpret_cast<uint2*>(g_Z8 + (size_t)row * DIM)[lid] = q;
}

// ---------------------------------------------------------------------------
// Kernel 2: e4m3 mma.sync GEMM + fused exp row-sums.
// grid 128: CTA -> (M-tile = bid>>1) x (column half = bid&1). A resident,
// B double-buffered via cp.async. Warp grid 4(M) x 2(N), warp tile 32x64.
// Row stride 272B -> ldmatrix 16B segments land on distinct banks.
// ---------------------------------------------------------------------------
__global__ void __launch_bounds__(256, 1) ntx_gemm_kernel() {
    extern __shared__ char smem[];
    uint32_t sb = smem_u32(smem);
    float* part = reinterpret_cast<float*>(smem);     // [2][128] rowsum partials
    const uint32_t Aoff = sb + 1024;
    const uint32_t Boff[2] = { Aoff + TILE8, Aoff + 2 * TILE8 };

    const int tid = threadIdx.x, wid = tid >> 5, lane = tid & 31;
    const int wm = wid >> 1, wn = wid & 1;
    const int mtile = blockIdx.x >> 1, half = blockIdx.x & 1;
    const int rowBase = mtile * TM, colBase = half * 4096;

    // A tile (128 x 256 e4m3 = 32KB), 8 CP16 per thread
    {
        const char* gsrc = reinterpret_cast<const char*>(g_Z8)
                         + (size_t)rowBase * DIM;
        #pragma unroll
        for (int i = 0; i < 8; i++) {
            int idx = tid + i * 256, r = idx >> 4, c = idx & 15;
            CP16(Aoff + r * RS8 + c * 16, gsrc + r * DIM + c * 16);
        }
        CP_COMMIT();
    }
    {
        const char* gsrc = reinterpret_cast<const char*>(g_Z8)
                         + (size_t)colBase * DIM;
        #pragma unroll
        for (int i = 0; i < 8; i++) {
            int idx = tid + i * 256, r = idx >> 4, c = idx & 15;
            CP16(Boff[0] + r * RS8 + c * 16, gsrc + r * DIM + c * 16);
        }
        CP_COMMIT();
    }

    // ldmatrix lane addresses (e4m3 k32 fragments, b16 ldmatrix on 16B rows)
    // A: matrices {rows0-7 k0-15}{rows8-15 k0-15}{rows0-7 k16-31}{rows8-15 k16-31}
    const uint32_t ArowRel = (uint32_t)((wm * 32 + (lane & 7)
                           + 8 * ((lane >> 3) & 1)) * RS8 + 16 * (lane >> 4));
    // B: matrices {cols0-7 k0-15}{cols0-7 k16-31}{cols8-15 k0-15}{cols8-15 k16-31}
    const uint32_t BrowRel = (uint32_t)((wn * 64 + (lane & 7)
                           + 8 * (lane >> 4)) * RS8 + 16 * ((lane >> 3) & 1));

    float rsum[2][2] = {{0.f, 0.f}, {0.f, 0.f}};

    for (int t = 0; t < TILES; t++) {
        const int buf = t & 1, nb = buf ^ 1;
        if (t + 1 < TILES) {
            const char* gsrc = reinterpret_cast<const char*>(g_Z8)
                             + (size_t)(colBase + (t + 1) * TN) * DIM;
            #pragma unroll
            for (int i = 0; i < 8; i++) {
                int idx = tid + i * 256, r = idx >> 4, c = idx & 15;
                CP16(Boff[nb] + r * RS8 + c * 16, gsrc + r * DIM + c * 16);
            }
            CP_COMMIT();
            CP_WAIT(1);
        } else {
            CP_WAIT(0);
        }
        __syncthreads();

        float acc[2][8][4];
        #pragma unroll
        for (int mt = 0; mt < 2; mt++)
            #pragma unroll
            for (int nt = 0; nt < 8; nt++)
                #pragma unroll
                for (int c = 0; c < 4; c++) acc[mt][nt][c] = 0.f;

        const uint32_t Arow = Aoff + ArowRel;
        const uint32_t Brow = Boff[buf] + BrowRel;
        #pragma unroll
        for (int ks = 0; ks < KSTEPS; ks++) {
            uint32_t a[2][4], b[4][4];
            #pragma unroll
            for (int mt = 0; mt < 2; mt++)
                LDSM_X4(a[mt][0], a[mt][1], a[mt][2], a[mt][3],
                        Arow + mt * 16 * RS8 + ks * 32);
            #pragma unroll
            for (int p = 0; p < 4; p++)
                LDSM_X4(b[p][0], b[p][1], b[p][2], b[p][3],
                        Brow + p * 16 * RS8 + ks * 32);
            #pragma unroll
            for (int mt = 0; mt < 2; mt++)
                #pragma unroll
                for (int p = 0; p < 4; p++) {
                    MMA_FP8(acc[mt][2 * p],     a[mt], b[p][0], b[p][1]);
                    MMA_FP8(acc[mt][2 * p + 1], a[mt], b[p][2], b[p][3]);
                }
        }

        // Register-only epilogue (before sync: overlaps other warps' MMAs).
        #pragma unroll
        for (int mt = 0; mt < 2; mt++) {
            float s0 = 0.f, s1 = 0.f;
            #pragma unroll
            for (int nt = 0; nt < 8; nt++) {
                float e;
                asm("ex2.approx.f32 %0, %1;" : "=f"(e)
                    : "f"(acc[mt][nt][0] * EXC)); s0 += e;
                asm("ex2.approx.f32 %0, %1;" : "=f"(e)
                    : "f"(acc[mt][nt][1] * EXC)); s0 += e;
                asm("ex2.approx.f32 %0, %1;" : "=f"(e)
                    : "f"(acc[mt][nt][2] * EXC)); s1 += e;
                asm("ex2.approx.f32 %0, %1;" : "=f"(e)
                    : "f"(acc[mt][nt][3] * EXC)); s1 += e;
            }
            rsum[mt][0] += s0;
            rsum[mt][1] += s1;
        }
        __syncthreads();            // B[buf] consumed before next fill
    }

    #pragma unroll
    for (int mt = 0; mt < 2; mt++)
        #pragma unroll
        for (int h = 0; h < 2; h++) {
            float v = rsum[mt][h];
            v += __shfl_xor_sync(0xffffffffu, v, 1);
            v += __shfl_xor_sync(0xffffffffu, v, 2);
            rsum[mt][h] = v;
        }
    if ((lane & 3) == 0) {
        int g = lane >> 2;
        #pragma unroll
        for (int mt = 0; mt < 2; mt++)
            #pragma unroll
            for (int h = 0; h < 2; h++)
                part[wn * 128 + wm * 32 + mt * 16 + h * 8 + g] = rsum[mt][h];
    }
    __syncthreads();
    if (tid < 128)
        g_rowsum[half][rowBase + tid] = part[tid] + part[128 + tid];
}

// ---------------------------------------------------------------------------
// Kernel 3: per-row loss. Self-dot from the SAME e4m3 data + same ex2.approx
// (cancels the in-sum diagonal term); positive from bf16 (accurate).
// ---------------------------------------------------------------------------
__global__ void ntx_loss_kernel() {
    int wid = threadIdx.x >> 5, lid = threadIdx.x & 31;
    int row = blockIdx.x * 8 + wid;
    int pos = (row < BATCH) ? row + BATCH : row - BATCH;

    uint2 q = reinterpret_cast<const uint2*>(g_Z8 + (size_t)row * DIM)[lid];
    float4 f0 = unpack_e4m3x4(q.x), f1 = unpack_e4m3x4(q.y);
    float dself = f0.x*f0.x + f0.y*f0.y + f0.z*f0.z + f0.w*f0.w
                + f1.x*f1.x + f1.y*f1.y + f1.z*f1.z + f1.w*f1.w;

    uint4 r4 = reinterpret_cast<const uint4*>(g_Zb + (size_t)row * DIM)[lid];
    uint4 p4 = reinterpret_cast<const uint4*>(g_Zb + (size_t)pos * DIM)[lid];
    const __nv_bfloat162* rp = reinterpret_cast<const __nv_bfloat162*>(&r4);
    const __nv_bfloat162* pp = reinterpret_cast<const __nv_bfloat162*>(&p4);
    float dpos = 0.f;
    #pragma unroll
    for (int j = 0; j < 4; j++) {
        float2 fr = __bfloat1622float2(rp[j]);
        float2 fp = __bfloat1622float2(pp[j]);
        dpos += fr.x * fp.x + fr.y * fp.y;
    }
    #pragma unroll
    for (int m = 16; m >= 1; m >>= 1) {
        dself += __shfl_xor_sync(0xffffffffu, dself, m);
        dpos  += __shfl_xor_sync(0xffffffffu, dpos,  m);
    }
    __shared__ float ls[8];
    if (lid == 0) {
        float diagterm;
        asm("ex2.approx.f32 %0, %1;" : "=f"(diagterm) : "f"(dself * EXC));
        float rsum = g_rowsum[0][row] + g_rowsum[1][row];
        ls[wid] = logf(rsum - diagterm) - 2.f * dpos;
    }
    __syncthreads();
    if (threadIdx.x == 0) {
        float s = 0.f;
        #pragma unroll
        for (int i = 0; i < 8; i++) s += ls[i];
        g_blocksum[blockIdx.x] = s;
    }
}

__global__ void ntx_final_kernel(float* __restrict__ out) {
    __shared__ float sm[256];
    int t = threadIdx.x;
    sm[t] = g_blocksum[t] + g_blocksum[t + 256]
          + g_blocksum[t + 512] + g_blocksum[t + 768];
    __syncthreads();
    for (int w = 128; w >= 1; w >>= 1) {
        if (t < w) sm[t] += sm[t + w];
        __syncthreads();
    }
    if (t == 0) out[0] = sm[0] / (float)NROWS;
}

// ---------------------------------------------------------------------------
extern "C" void kernel_launch(void* const* d_in, const int* in_sizes, int n_in,
                              void* d_out, int out_size) {
    const float* zi = (const float*)d_in[0];
    const float* zj = (const float*)d_in[1];
    float* out = (float*)d_out;

    const int smem_bytes = 1024 + 3 * TILE8;   // 105472
    cudaFuncSetAttribute(ntx_gemm_kernel,
                         cudaFuncAttributeMaxDynamicSharedMemorySize, smem_bytes);

    ntx_norm_kernel<<<1024, 256>>>(zi, zj);
    ntx_gemm_kernel<<<128, 256, smem_bytes>>>();
    ntx_loss_kernel<<<1024, 256>>>();
    ntx_final_kernel<<<1, 256>>>(out);
}

// round 6
// speedup vs baseline: 18.7015x; 1.6235x over previous
#include <cuda_runtime.h>
#include <cuda_bf16.h>
#include <cuda_fp16.h>
#include <cstdint>

#define BATCH   4096
#define DIM     256
#define NROWS   8192
#define NT      64            // 64x64 grid of 128x128 tiles
#define NTILES_UT 2080        // NT*(NT+1)/2
#define KSTEPS  8             // K=256 / k32
#define RS8     272           // smem row stride bytes (256 + 16 pad)
#define TILE8   (128 * RS8)   // 34816 B per tile
// logits = dot/T = acc/(16*16)*2 ; ex2 arg = acc * 2*log2(e)/256
#define EXC     0.011271055006945026f

// Scratch (no allocations allowed)
__device__ __nv_bfloat16 g_Zb[NROWS * DIM];     // normalized rows, bf16
__device__ uint8_t g_Z8[NROWS * DIM];           // normalized rows * 16, e4m3
__device__ float g_scratch[NT * NT * 128];      // [I*64+J][r]: block contribs (2MB)
__device__ float g_blocksum[1024];

__device__ __forceinline__ uint32_t smem_u32(const void* p) {
    uint32_t a;
    asm("{ .reg .u64 t; cvta.to.shared.u64 t, %1; cvt.u32.u64 %0, t; }"
        : "=r"(a) : "l"(p));
    return a;
}
#define CP16(dst, src) \
    asm volatile("cp.async.cg.shared.global [%0], [%1], 16;" \
                 :: "r"(dst), "l"(src) : "memory")
#define CP_COMMIT() asm volatile("cp.async.commit_group;" ::: "memory")
#define CP_WAIT(n)  asm volatile("cp.async.wait_group %0;" :: "n"(n) : "memory")

#define LDSM_X4(r0, r1, r2, r3, a)                                         \
    asm volatile("ldmatrix.sync.aligned.m8n8.x4.shared.b16 "               \
                 "{%0,%1,%2,%3}, [%4];"                                    \
                 : "=r"(r0), "=r"(r1), "=r"(r2), "=r"(r3) : "r"(a))

#define MMA_FP8(c, a, b0, b1)                                              \
    asm volatile("mma.sync.aligned.m16n8k32.row.col.f32.e4m3.e4m3.f32 "    \
                 "{%0,%1,%2,%3}, {%4,%5,%6,%7}, {%8,%9}, {%0,%1,%2,%3};"   \
                 : "+f"((c)[0]), "+f"((c)[1]), "+f"((c)[2]), "+f"((c)[3])  \
                 : "r"((a)[0]), "r"((a)[1]), "r"((a)[2]), "r"((a)[3]),     \
                   "r"(b0), "r"(b1))

__device__ __forceinline__ uint32_t pack_e4m3x4(float x0, float x1,
                                                float x2, float x3) {
    uint32_t w;
    asm("{ .reg .b16 s0, s1;\n\t"
        "cvt.rn.satfinite.e4m3x2.f32 s0, %2, %1;\n\t"
        "cvt.rn.satfinite.e4m3x2.f32 s1, %4, %3;\n\t"
        "mov.b32 %0, {s0, s1}; }"
        : "=r"(w) : "f"(x0), "f"(x1), "f"(x2), "f"(x3));
    return w;
}
__device__ __forceinline__ float4 unpack_e4m3x4(uint32_t w) {
    uint32_t h0, h1;
    asm("{ .reg .b16 a, b;\n\t"
        "mov.b32 {a, b}, %2;\n\t"
        "cvt.rn.f16x2.e4m3x2 %0, a;\n\t"
        "cvt.rn.f16x2.e4m3x2 %1, b; }"
        : "=r"(h0), "=r"(h1) : "r"(w));
    __half2 v0 = *reinterpret_cast<__half2*>(&h0);
    __half2 v1 = *reinterpret_cast<__half2*>(&h1);
    float2 f0 = __half22float2(v0), f1 = __half22float2(v1);
    return make_float4(f0.x, f0.y, f1.x, f1.y);
}

// ---------------------------------------------------------------------------
// Kernel 1: L2-normalize rows -> bf16 (exact path) + e4m3*16 (GEMM path).
// ---------------------------------------------------------------------------
__global__ void ntx_norm_kernel(const float* __restrict__ zi,
                                const float* __restrict__ zj) {
    int wid = threadIdx.x >> 5, lid = threadIdx.x & 31;
    int row = blockIdx.x * 8 + wid;
    const float* src = (row < BATCH) ? (zi + (size_t)row * DIM)
                                     : (zj + (size_t)(row - BATCH) * DIM);
    float4 a = reinterpret_cast<const float4*>(src)[lid * 2];
    float4 b = reinterpret_cast<const float4*>(src)[lid * 2 + 1];
    float ss = a.x*a.x + a.y*a.y + a.z*a.z + a.w*a.w
             + b.x*b.x + b.y*b.y + b.z*b.z + b.w*b.w;
    #pragma unroll
    for (int m = 16; m >= 1; m >>= 1) ss += __shfl_xor_sync(0xffffffffu, ss, m);
    float inv = rsqrtf(ss);
    float s16 = inv * 16.0f;

    __nv_bfloat162 p0 = __floats2bfloat162_rn(a.x*inv, a.y*inv);
    __nv_bfloat162 p1 = __floats2bfloat162_rn(a.z*inv, a.w*inv);
    __nv_bfloat162 p2 = __floats2bfloat162_rn(b.x*inv, b.y*inv);
    __nv_bfloat162 p3 = __floats2bfloat162_rn(b.z*inv, b.w*inv);
    uint4 o;
    o.x = *(uint32_t*)&p0; o.y = *(uint32_t*)&p1;
    o.z = *(uint32_t*)&p2; o.w = *(uint32_t*)&p3;
    reinterpret_cast<uint4*>(g_Zb + (size_t)row * DIM)[lid] = o;

    uint2 q;
    q.x = pack_e4m3x4(a.x*s16, a.y*s16, a.z*s16, a.w*s16);
    q.y = pack_e4m3x4(b.x*s16, b.y*s16, b.z*s16, b.w*s16);
    reinterpret_cast<uint2*>(g_Z8 + (size_t)row * DIM)[lid] = q;
}

// ---------------------------------------------------------------------------
// Kernel 2: symmetric e4m3 GEMM. One CTA per upper-triangle 128x128 tile
// (I,J), J>=I. Row-sums of exp -> block I; col-sums (= mirrored tile's
// row-sums) -> block J. Deterministic scatter into g_scratch[I*64+J].
// ---------------------------------------------------------------------------
__global__ void __launch_bounds__(256) ntx_gemm_kernel() {
    extern __shared__ char smem[];
    uint32_t sb = smem_u32(smem);
    float* rowpart = reinterpret_cast<float*>(smem);        // [2][128]
    float* colpart = reinterpret_cast<float*>(smem) + 256;  // [4][128]
    const uint32_t Aoff = sb + 4096;
    const uint32_t BoffR = Aoff + TILE8;

    // bid -> (I, J) in upper triangle: cum(I) = 64I - I(I-1)/2
    const int t = blockIdx.x;
    int I = (int)((129.0f - sqrtf(129.0f * 129.0f - 8.0f * (float)t)) * 0.5f);
    if (I > 63) I = 63;
    if (I < 0) I = 0;
    while (64 * (I + 1) - ((I + 1) * I) / 2 <= t) ++I;
    while (64 * I - (I * (I - 1)) / 2 > t) --I;
    const int J = I + (t - (64 * I - (I * (I - 1)) / 2));
    const bool diag = (I == J);
    const uint32_t Boff = diag ? Aoff : BoffR;

    const int tid = threadIdx.x, wid = tid >> 5, lane = tid & 31;
    const int wm = wid >> 1, wn = wid & 1;

    // load A (and B if off-diagonal)
    {
        const char* gsrc = reinterpret_cast<const char*>(g_Z8)
                         + (size_t)I * 128 * DIM;
        #pragma unroll
        for (int i = 0; i < 8; i++) {
            int idx = tid + i * 256, r = idx >> 4, c = idx & 15;
            CP16(Aoff + r * RS8 + c * 16, gsrc + r * DIM + c * 16);
        }
    }
    if (!diag) {
        const char* gsrc = reinterpret_cast<const char*>(g_Z8)
                         + (size_t)J * 128 * DIM;
        #pragma unroll
        for (int i = 0; i < 8; i++) {
            int idx = tid + i * 256, r = idx >> 4, c = idx & 15;
            CP16(BoffR + r * RS8 + c * 16, gsrc + r * DIM + c * 16);
        }
    }
    CP_COMMIT();
    CP_WAIT(0);
    __syncthreads();

    // fragment addresses (validated layout from round 5)
    const uint32_t Arow = Aoff + (uint32_t)((wm * 32 + (lane & 7)
                        + 8 * ((lane >> 3) & 1)) * RS8 + 16 * (lane >> 4));
    const uint32_t Brow = Boff + (uint32_t)((wn * 64 + (lane & 7)
                        + 8 * (lane >> 4)) * RS8 + 16 * ((lane >> 3) & 1));

    float acc[2][8][4];
    #pragma unroll
    for (int mt = 0; mt < 2; mt++)
        #pragma unroll
        for (int nt = 0; nt < 8; nt++)
            #pragma unroll
            for (int c = 0; c < 4; c++) acc[mt][nt][c] = 0.f;

    #pragma unroll
    for (int ks = 0; ks < KSTEPS; ks++) {
        uint32_t a[2][4], b[4][4];
        #pragma unroll
        for (int mt = 0; mt < 2; mt++)
            LDSM_X4(a[mt][0], a[mt][1], a[mt][2], a[mt][3],
                    Arow + mt * 16 * RS8 + ks * 32);
        #pragma unroll
        for (int p = 0; p < 4; p++)
            LDSM_X4(b[p][0], b[p][1], b[p][2], b[p][3],
                    Brow + p * 16 * RS8 + ks * 32);
        #pragma unroll
        for (int mt = 0; mt < 2; mt++)
            #pragma unroll
            for (int p = 0; p < 4; p++) {
                MMA_FP8(acc[mt][2 * p],     a[mt], b[p][0], b[p][1]);
                MMA_FP8(acc[mt][2 * p + 1], a[mt], b[p][2], b[p][3]);
            }
    }

    // exp in place: fragment (mt,nt,c): row = wm*32+mt*16 + g(+8 for c>=2),
    // col = wn*64+nt*8 + 2q + (c&1);  g=lane>>2, q=lane&3.
    #pragma unroll
    for (int mt = 0; mt < 2; mt++)
        #pragma unroll
        for (int nt = 0; nt < 8; nt++)
            #pragma unroll
            for (int c = 0; c < 4; c++)
                asm("ex2.approx.f32 %0, %1;" : "+f"(acc[mt][nt][c])
                    : "f"(acc[mt][nt][c] * EXC));

    // ---- row sums (over tile cols) ----
    #pragma unroll
    for (int mt = 0; mt < 2; mt++) {
        float s0 = 0.f, s1 = 0.f;
        #pragma unroll
        for (int nt = 0; nt < 8; nt++) {
            s0 += acc[mt][nt][0] + acc[mt][nt][1];
            s1 += acc[mt][nt][2] + acc[mt][nt][3];
        }
        s0 += __shfl_xor_sync(0xffffffffu, s0, 1);
        s0 += __shfl_xor_sync(0xffffffffu, s0, 2);
        s1 += __shfl_xor_sync(0xffffffffu, s1, 1);
        s1 += __shfl_xor_sync(0xffffffffu, s1, 2);
        if ((lane & 3) == 0) {
            int g = lane >> 2;
            rowpart[wn * 128 + wm * 32 + mt * 16 + g]     = s0;
            rowpart[wn * 128 + wm * 32 + mt * 16 + 8 + g] = s1;
        }
    }

    // ---- col sums (over tile rows) -> mirrored-tile row sums ----
    if (!diag) {
        #pragma unroll
        for (int nt = 0; nt < 8; nt++) {
            float c0 = acc[0][nt][0] + acc[0][nt][2]
                     + acc[1][nt][0] + acc[1][nt][2];
            float c1 = acc[0][nt][1] + acc[0][nt][3]
                     + acc[1][nt][1] + acc[1][nt][3];
            c0 += __shfl_xor_sync(0xffffffffu, c0, 4);
            c0 += __shfl_xor_sync(0xffffffffu, c0, 8);
            c0 += __shfl_xor_sync(0xffffffffu, c0, 16);
            c1 += __shfl_xor_sync(0xffffffffu, c1, 4);
            c1 += __shfl_xor_sync(0xffffffffu, c1, 8);
            c1 += __shfl_xor_sync(0xffffffffu, c1, 16);
            if (lane < 4) {
                colpart[wm * 128 + wn * 64 + nt * 8 + 2 * lane]     = c0;
                colpart[wm * 128 + wn * 64 + nt * 8 + 2 * lane + 1] = c1;
            }
        }
    }
    __syncthreads();

    if (tid < 128) {
        g_scratch[(size_t)(I * NT + J) * 128 + tid]
            = rowpart[tid] + rowpart[128 + tid];
        if (!diag)
            g_scratch[(size_t)(J * NT + I) * 128 + tid]
                = colpart[tid] + colpart[128 + tid]
                + colpart[256 + tid] + colpart[384 + tid];
    }
}

// ---------------------------------------------------------------------------
// Kernel 3: per-row loss. rowsum = sum of 64 block contributions; self-dot
// from the SAME e4m3 data + same ex2.approx (cancels the in-sum diag term);
// positive from bf16. Warp per row.
// ---------------------------------------------------------------------------
__global__ void ntx_loss_kernel() {
    int wid = threadIdx.x >> 5, lid = threadIdx.x & 31;
    int row = blockIdx.x * 8 + wid;
    int pos = (row < BATCH) ? row + BATCH : row - BATCH;
    int I = row >> 7, r = row & 127;

    float rsum = g_scratch[(size_t)(I * NT + lid) * 128 + r]
               + g_scratch[(size_t)(I * NT + lid + 32) * 128 + r];

    uint2 q = reinterpret_cast<const uint2*>(g_Z8 + (size_t)row * DIM)[lid];
    float4 f0 = unpack_e4m3x4(q.x), f1 = unpack_e4m3x4(q.y);
    float dself = f0.x*f0.x + f0.y*f0.y + f0.z*f0.z + f0.w*f0.w
                + f1.x*f1.x + f1.y*f1.y + f1.z*f1.z + f1.w*f1.w;

    uint4 r4 = reinterpret_cast<const uint4*>(g_Zb + (size_t)row * DIM)[lid];
    uint4 p4 = reinterpret_cast<const uint4*>(g_Zb + (size_t)pos * DIM)[lid];
    const __nv_bfloat162* rp = reinterpret_cast<const __nv_bfloat162*>(&r4);
    const __nv_bfloat162* pp = reinterpret_cast<const __nv_bfloat162*>(&p4);
    float dpos = 0.f;
    #pragma unroll
    for (int j = 0; j < 4; j++) {
        float2 fr = __bfloat1622float2(rp[j]);
        float2 fp = __bfloat1622float2(pp[j]);
        dpos += fr.x * fp.x + fr.y * fp.y;
    }
    #pragma unroll
    for (int m = 16; m >= 1; m >>= 1) {
        rsum  += __shfl_xor_sync(0xffffffffu, rsum,  m);
        dself += __shfl_xor_sync(0xffffffffu, dself, m);
        dpos  += __shfl_xor_sync(0xffffffffu, dpos,  m);
    }
    __shared__ float ls[8];
    if (lid == 0) {
        float diagterm;
        asm("ex2.approx.f32 %0, %1;" : "=f"(diagterm) : "f"(dself * EXC));
        ls[wid] = logf(rsum - diagterm) - 2.f * dpos;
    }
    __syncthreads();
    if (threadIdx.x == 0) {
        float s = 0.f;
        #pragma unroll
        for (int i = 0; i < 8; i++) s += ls[i];
        g_blocksum[blockIdx.x] = s;
    }
}

__global__ void ntx_final_kernel(float* __restrict__ out) {
    __shared__ float sm[256];
    int t = threadIdx.x;
    sm[t] = g_blocksum[t] + g_blocksum[t + 256]
          + g_blocksum[t + 512] + g_blocksum[t + 768];
    __syncthreads();
    for (int w = 128; w >= 1; w >>= 1) {
        if (t < w) sm[t] += sm[t + w];
        __syncthreads();
    }
    if (t == 0) out[0] = sm[0] / (float)NROWS;
}

// ---------------------------------------------------------------------------
extern "C" void kernel_launch(void* const* d_in, const int* in_sizes, int n_in,
                              void* d_out, int out_size) {
    const float* zi = (const float*)d_in[0];
    const float* zj = (const float*)d_in[1];
    float* out = (float*)d_out;

    const int smem_bytes = 4096 + 2 * TILE8;   // 73728
    cudaFuncSetAttribute(ntx_gemm_kernel,
                         cudaFuncAttributeMaxDynamicSharedMemorySize, smem_bytes);

    ntx_norm_kernel<<<1024, 256>>>(zi, zj);
    ntx_gemm_kernel<<<NTILES_UT, 256, smem_bytes>>>();
    ntx_loss_kernel<<<1024, 256>>>();
    ntx_final_kernel<<<1, 256>>>(out);
}